// round 10
// baseline (speedup 1.0000x reference)
#include <cuda_runtime.h>
#include <cuda_bf16.h>
#include <stdint.h>
#include <math.h>

// CosineAttention: out = sigmoid( (X X^T / max(n_i n_j, eps)) X )
// N=8192, D=1024, fp32.
//
// Harness targets plain sm_103 (no 'a' features): tcgen05/TMA unavailable.
// => mma.sync.m16n8k16 bf16 path with hi/lo split (3-MMA fp32 emulation),
//    cp.async double-buffered smem, ldmatrix fragment loads.
//   prep:  norms; Xhat = X/||row|| -> (Xhi,Xlo); X^T (unscaled) -> (XThi,XTlo)
//   gemm1: S = Xhat Xhat^T -> bf16 hi/lo split scratch (== cosine sim matrix;
//          eps guard never binds for normal data, norms ~32).
//          SYMMETRIC: only bi<=bj tiles computed; off-diagonal tiles are
//          mirrored to (bj,bi) via an smem-bounce transpose.
//   gemm2: out = sigmoid(S X) -> fp32

#define NROWS 8192
#define DDIM  1024

// ---- scratch (allocation-free rule => __device__ globals) ------------------
__device__ __nv_bfloat16 g_Xhi[(size_t)NROWS * DDIM];    // scaled rows
__device__ __nv_bfloat16 g_Xlo[(size_t)NROWS * DDIM];
__device__ __nv_bfloat16 g_XThi[(size_t)DDIM * NROWS];   // unscaled transpose
__device__ __nv_bfloat16 g_XTlo[(size_t)DDIM * NROWS];
__device__ __nv_bfloat16 g_Shi[(size_t)NROWS * NROWS];
__device__ __nv_bfloat16 g_Slo[(size_t)NROWS * NROWS];
__device__ float g_rinv[NROWS];

// ---- helpers ---------------------------------------------------------------
__device__ __forceinline__ uint32_t smem_u32(const void* p) {
    uint32_t a;
    asm("{ .reg .u64 t; cvta.to.shared.u64 t, %1; cvt.u32.u64 %0, t; }"
        : "=r"(a) : "l"(p));
    return a;
}

__device__ __forceinline__ void cp_async16(uint32_t dst, const void* src) {
    asm volatile("cp.async.cg.shared.global [%0], [%1], 16;" :: "r"(dst), "l"(src));
}
#define CP_COMMIT() asm volatile("cp.async.commit_group;" ::: "memory")
#define CP_WAIT0()  asm volatile("cp.async.wait_group 0;" ::: "memory")
#define CP_WAIT1()  asm volatile("cp.async.wait_group 1;" ::: "memory")

__device__ __forceinline__ void ldsm4(uint32_t* r, uint32_t addr) {
    asm volatile("ldmatrix.sync.aligned.m8n8.x4.shared.b16 {%0,%1,%2,%3}, [%4];"
                 : "=r"(r[0]), "=r"(r[1]), "=r"(r[2]), "=r"(r[3]) : "r"(addr));
}

__device__ __forceinline__ void mma16816(float* c, const uint32_t* a,
                                         uint32_t b0, uint32_t b1) {
    asm volatile(
        "mma.sync.aligned.m16n8k16.row.col.f32.bf16.bf16.f32 "
        "{%0,%1,%2,%3}, {%4,%5,%6,%7}, {%8,%9}, {%0,%1,%2,%3};"
        : "+f"(c[0]), "+f"(c[1]), "+f"(c[2]), "+f"(c[3])
        : "r"(a[0]), "r"(a[1]), "r"(a[2]), "r"(a[3]), "r"(b0), "r"(b1));
}

// ---- tiling ----------------------------------------------------------------
#define BM 128
#define BN 128
#define BK 32
#define LDS_E 40                    // smem row stride in elements (80 B, 16B-mult)
#define ATILE_B (128 * LDS_E * 2)   // 10240 B per tile
#define STAGE_B (4 * ATILE_B)       // Ahi,Alo,Bhi,Blo
#define DSMEM_BYTES (2 * STAGE_B)   // 81920 B
#define O_AHI 0
#define O_ALO ATILE_B
#define O_BHI (2 * ATILE_B)
#define O_BLO (3 * ATILE_B)

// ---------------------------------------------------------------------------
// Kernel 0: reciprocal row norms.
// ---------------------------------------------------------------------------
__global__ void norms_kernel(const float* __restrict__ x) {
    int row  = blockIdx.x * 8 + threadIdx.y;
    int lane = threadIdx.x;
    const float4* xr = reinterpret_cast<const float4*>(x + (size_t)row * DDIM);
    float s = 0.0f;
    #pragma unroll
    for (int i = 0; i < 8; i++) {
        float4 v = xr[lane + i * 32];
        s += v.x * v.x + v.y * v.y + v.z * v.z + v.w * v.w;
    }
    #pragma unroll
    for (int o = 16; o > 0; o >>= 1) s += __shfl_xor_sync(0xffffffffu, s, o);
    if (lane == 0) g_rinv[row] = 1.0f / sqrtf(s);
}

// ---------------------------------------------------------------------------
// Kernel 0b: split. Row-major scaled (Xhat), transposed unscaled (X^T).
// ---------------------------------------------------------------------------
__global__ void split_kernel(const float* __restrict__ x) {
    __shared__ __nv_bfloat16 thi[32][33];
    __shared__ __nv_bfloat16 tlo[32][33];
    int d0 = blockIdx.x * 32;
    int n0 = blockIdx.y * 32;
    int tx = threadIdx.x, ty = threadIdx.y;

    #pragma unroll
    for (int r = 0; r < 4; r++) {
        int n = ty + r * 8;
        size_t gi = (size_t)(n0 + n) * DDIM + d0 + tx;
        float f = x[gi];
        // unscaled -> transpose staging
        __nv_bfloat16 uhi = __float2bfloat16(f);
        thi[n][tx] = uhi;
        tlo[n][tx] = __float2bfloat16(f - __bfloat162float(uhi));
        // scaled -> row-major
        float fs = f * g_rinv[n0 + n];
        __nv_bfloat16 shi = __float2bfloat16(fs);
        g_Xhi[gi] = shi;
        g_Xlo[gi] = __float2bfloat16(fs - __bfloat162float(shi));
    }
    __syncthreads();
    #pragma unroll
    for (int r = 0; r < 4; r++) {
        int d = ty + r * 8;
        size_t go = (size_t)(d0 + d) * NROWS + n0 + tx;
        g_XThi[go] = thi[tx][d];
        g_XTlo[go] = tlo[tx][d];
    }
}

// ---------------------------------------------------------------------------
// Mainloop: double-buffered cp.async + 3-pass bf16 mma.sync.
// A,B: 128-row K-major bf16 tiles. acc[2][8][4] per thread.
// Warp grid 4(M)x2(N); warp tile 32x64.
// ---------------------------------------------------------------------------
struct GemmPtrs {
    const __nv_bfloat16 *Ahi, *Alo, *Bhi, *Blo;
};

__device__ __forceinline__ void load_stage(
    uint8_t* smem, int stage, const GemmPtrs& P, size_t ldK, int k0, int tid)
{
    uint32_t sb = smem_u32(smem + stage * STAGE_B);
    const __nv_bfloat16* srcs[4] = {P.Ahi, P.Alo, P.Bhi, P.Blo};
    const int rbase = tid >> 2;        // 0..63
    const int ch    = tid & 3;         // 16B chunk within 64-elem row span
    #pragma unroll
    for (int t = 0; t < 8; t++) {
        const int tile = t >> 1;       // COMPILE-TIME constant per iteration
        const int row  = (t & 1) * 64 + rbase;
        uint32_t daddr = sb + tile * ATILE_B + row * (LDS_E * 2) + ch * 16;
        const __nv_bfloat16* g = srcs[tile] + (size_t)row * ldK + k0 + ch * 8;
        cp_async16(daddr, g);
    }
}

__device__ __forceinline__ void compute_stage(
    uint8_t* smem, int stage, float acc[2][8][4],
    int wm, int wn, int lane)
{
    uint32_t sb = smem_u32(smem + stage * STAGE_B);
    int arow = wm * 32 + (lane & 15);            // + mi*16
    int acol8 = (lane >> 4) << 3;                // 0 or 8
    int brow = wn * 64 + (lane & 7) + ((lane >> 3) & 1) * 8;   // + n2*16
    int bcol8 = (lane >> 4) << 3;

    #pragma unroll
    for (int ks = 0; ks < BK; ks += 16) {
        uint32_t ahi[2][4], alo[2][4];
        #pragma unroll
        for (int mi = 0; mi < 2; mi++) {
            uint32_t off = (arow + mi * 16) * (LDS_E * 2) + (ks + acol8) * 2;
            ldsm4(ahi[mi], sb + O_AHI + off);
            ldsm4(alo[mi], sb + O_ALO + off);
        }
        uint32_t bhi[4][4], blo[4][4];
        #pragma unroll
        for (int n2 = 0; n2 < 4; n2++) {
            uint32_t off = (brow + n2 * 16) * (LDS_E * 2) + (ks + bcol8) * 2;
            ldsm4(bhi[n2], sb + O_BHI + off);
            ldsm4(blo[n2], sb + O_BLO + off);
        }
        #pragma unroll
        for (int mi = 0; mi < 2; mi++) {
            #pragma unroll
            for (int ni = 0; ni < 8; ni++) {
                int n2 = ni >> 1, o = ni & 1;
                uint32_t bh0 = bhi[n2][o], bh1 = bhi[n2][o + 2];
                uint32_t bl0 = blo[n2][o], bl1 = blo[n2][o + 2];
                mma16816(acc[mi][ni], ahi[mi], bh0, bh1);   // hi*hi
                mma16816(acc[mi][ni], ahi[mi], bl0, bl1);   // hi*lo
                mma16816(acc[mi][ni], alo[mi], bh0, bh1);   // lo*hi
            }
        }
    }
}

__device__ __forceinline__ void gemm_mainloop(
    uint8_t* smem, float acc[2][8][4], const GemmPtrs& P, size_t ldK,
    int NCH, int tid, int wm, int wn, int lane)
{
    load_stage(smem, 0, P, ldK, 0, tid);
    CP_COMMIT();
    for (int ch = 0; ch < NCH; ch++) {
        if (ch + 1 < NCH) {
            load_stage(smem, (ch + 1) & 1, P, ldK, (ch + 1) * BK, tid);
            CP_COMMIT();
            CP_WAIT1();
        } else {
            CP_WAIT0();
        }
        __syncthreads();
        compute_stage(smem, ch & 1, acc, wm, wn, lane);
        __syncthreads();
    }
}

// ---------------------------------------------------------------------------
// Kernel 1: S = Xhat Xhat^T, stored bf16 hi/lo. Upper-triangular only;
// off-diagonal tiles mirrored to (bj,bi) via smem-bounce transpose.
// ---------------------------------------------------------------------------
__global__ __launch_bounds__(256, 2) void gemm1_kernel() {
    extern __shared__ uint8_t smem[];
    const int bi = blockIdx.y, bj = blockIdx.x;
    if (bi > bj) return;   // uniform per-CTA: lower triangle handled by mirror

    const int tid  = threadIdx.x;
    const int lane = tid & 31;
    const int w    = tid >> 5;
    const int wm   = w & 3, wn = w >> 2;

    float acc[2][8][4];
    #pragma unroll
    for (int i = 0; i < 2; i++)
        #pragma unroll
        for (int j = 0; j < 8; j++)
            #pragma unroll
            for (int k = 0; k < 4; k++) acc[i][j][k] = 0.0f;

    GemmPtrs P;
    P.Ahi = g_Xhi + (size_t)(bi * BM) * DDIM;
    P.Alo = g_Xlo + (size_t)(bi * BM) * DDIM;
    P.Bhi = g_Xhi + (size_t)(bj * BN) * DDIM;
    P.Blo = g_Xlo + (size_t)(bj * BN) * DDIM;

    gemm_mainloop(smem, acc, P, DDIM, DDIM / BK, tid, wm, wn, lane);

    // Normal epilogue: write tile (bi, bj). acc IS the cosine similarity.
    int r0 = wm * 32 + (lane >> 2);
    int c0 = wn * 64 + (lane & 3) * 2;
    #pragma unroll
    for (int mi = 0; mi < 2; mi++) {
        #pragma unroll
        for (int half = 0; half < 2; half++) {
            int ig = bi * BM + r0 + mi * 16 + half * 8;
            size_t rowoff = (size_t)ig * NROWS;
            #pragma unroll
            for (int nj = 0; nj < 8; nj++) {
                int j = bj * BN + c0 + nj * 8;
                float f0 = acc[mi][nj][half * 2 + 0];
                float f1 = acc[mi][nj][half * 2 + 1];
                __nv_bfloat16 h0 = __float2bfloat16(f0);
                __nv_bfloat16 h1 = __float2bfloat16(f1);
                __nv_bfloat162 ph, pl;
                ph.x = h0; ph.y = h1;
                pl.x = __float2bfloat16(f0 - __bfloat162float(h0));
                pl.y = __float2bfloat16(f1 - __bfloat162float(h1));
                *reinterpret_cast<__nv_bfloat162*>(g_Shi + rowoff + j) = ph;
                *reinterpret_cast<__nv_bfloat162*>(g_Slo + rowoff + j) = pl;
            }
        }
    }

    // Mirror epilogue: tile (bj, bi) = transpose, via smem bounce.
    if (bi != bj) {
        const int LDT = 136;   // 272 B rows (16B multiple -> aligned uint4 reads)
        __nv_bfloat16* smT = reinterpret_cast<__nv_bfloat16*>(smem); // [128][LDT]
        const int oc = tid >> 1;      // mirrored row index (= original col)
        const int oh = tid & 1;       // half of 128 cols
        __nv_bfloat16* dsts[2] = {g_Shi, g_Slo};

        #pragma unroll
        for (int phase = 0; phase < 2; phase++) {
            __syncthreads();   // smem free (mainloop done / prev gather done)
            // Scatter transposed: smT[c][r] = hi or lo part of acc.
            #pragma unroll
            for (int mi = 0; mi < 2; mi++) {
                #pragma unroll
                for (int half = 0; half < 2; half++) {
                    int r = r0 + mi * 16 + half * 8;
                    #pragma unroll
                    for (int nj = 0; nj < 8; nj++) {
                        int c = c0 + nj * 8;
                        float f0 = acc[mi][nj][half * 2 + 0];
                        float f1 = acc[mi][nj][half * 2 + 1];
                        __nv_bfloat16 v0, v1;
                        if (phase == 0) {
                            v0 = __float2bfloat16(f0);
                            v1 = __float2bfloat16(f1);
                        } else {
                            __nv_bfloat16 h0 = __float2bfloat16(f0);
                            __nv_bfloat16 h1 = __float2bfloat16(f1);
                            v0 = __float2bfloat16(f0 - __bfloat162float(h0));
                            v1 = __float2bfloat16(f1 - __bfloat162float(h1));
                        }
                        smT[(c + 0) * LDT + r] = v0;
                        smT[(c + 1) * LDT + r] = v1;
                    }
                }
            }
            __syncthreads();
            // Gather rows of smT -> contiguous global rows of tile (bj, bi).
            __nv_bfloat16* dst = dsts[phase]
                + (size_t)(bj * BN + oc) * NROWS + bi * BM + oh * 64;
            const uint8_t* srow = reinterpret_cast<const uint8_t*>(
                smT + oc * LDT + oh * 64);
            #pragma unroll
            for (int k = 0; k < 8; k++) {
                *reinterpret_cast<uint4*>(dst + k * 8) =
                    *reinterpret_cast<const uint4*>(srow + k * 16);
            }
        }
    }
}

// ---------------------------------------------------------------------------
// Kernel 2: out = sigmoid(S @ X). A=S (hi/lo), B=XT unscaled (hi/lo), K=8192.
// ---------------------------------------------------------------------------
__global__ __launch_bounds__(256, 2) void gemm2_kernel(float* __restrict__ out) {
    extern __shared__ uint8_t smem[];
    const int tid  = threadIdx.x;
    const int lane = tid & 31;
    const int w    = tid >> 5;
    const int wm   = w & 3, wn = w >> 2;
    const int bm = blockIdx.y, bn = blockIdx.x;

    float acc[2][8][4];
    #pragma unroll
    for (int i = 0; i < 2; i++)
        #pragma unroll
        for (int j = 0; j < 8; j++)
            #pragma unroll
            for (int k = 0; k < 4; k++) acc[i][j][k] = 0.0f;

    GemmPtrs P;
    P.Ahi = g_Shi + (size_t)(bm * BM) * NROWS;
    P.Alo = g_Slo + (size_t)(bm * BM) * NROWS;
    P.Bhi = g_XThi + (size_t)(bn * BN) * NROWS;
    P.Blo = g_XTlo + (size_t)(bn * BN) * NROWS;

    gemm_mainloop(smem, acc, P, NROWS, NROWS / BK, tid, wm, wn, lane);

    int r0 = wm * 32 + (lane >> 2);
    int c0 = wn * 64 + (lane & 3) * 2;
    #pragma unroll
    for (int mi = 0; mi < 2; mi++) {
        #pragma unroll
        for (int half = 0; half < 2; half++) {
            int ig = bm * BM + r0 + mi * 16 + half * 8;
            size_t rowoff = (size_t)ig * DDIM;
            #pragma unroll
            for (int nj = 0; nj < 8; nj++) {
                int j = bn * BN + c0 + nj * 8;
                float2 v;
                v.x = 1.0f / (1.0f + __expf(-acc[mi][nj][half * 2 + 0]));
                v.y = 1.0f / (1.0f + __expf(-acc[mi][nj][half * 2 + 1]));
                *reinterpret_cast<float2*>(out + rowoff + j) = v;
            }
        }
    }
}

// ---------------------------------------------------------------------------
extern "C" void kernel_launch(void* const* d_in, const int* in_sizes, int n_in,
                              void* d_out, int out_size) {
    const float* x = (const float*)d_in[0];
    float* out = (float*)d_out;

    cudaFuncSetAttribute(gemm1_kernel,
                         cudaFuncAttributeMaxDynamicSharedMemorySize, DSMEM_BYTES);
    cudaFuncSetAttribute(gemm2_kernel,
                         cudaFuncAttributeMaxDynamicSharedMemorySize, DSMEM_BYTES);

    norms_kernel<<<NROWS / 8, dim3(32, 8)>>>(x);
    split_kernel<<<dim3(DDIM / 32, NROWS / 32), dim3(32, 8)>>>(x);
    gemm1_kernel<<<dim3(NROWS / BN, NROWS / BM), 256, DSMEM_BYTES>>>();
    gemm2_kernel<<<dim3(DDIM / BN, NROWS / BM), 256, DSMEM_BYTES>>>(out);
}

// round 13
// speedup vs baseline: 1.0180x; 1.0180x over previous
#include <cuda_runtime.h>
#include <cuda_bf16.h>
#include <stdint.h>
#include <math.h>

// CosineAttention: out = sigmoid( (X X^T / max(n_i n_j, eps)) X )
// N=8192, D=1024, fp32.
//
// mma.sync.m16n8k16 bf16 path with hi/lo split (3-MMA fp32 emulation),
// cp.async double-buffered smem (ONE barrier per chunk), ldmatrix loads.
//   prep:  norms; Xhat = X/||row|| -> (Xhi,Xlo); X^T (unscaled) -> (XThi,XTlo)
//   gemm1: S = Xhat Xhat^T -> bf16 hi/lo split scratch. SYMMETRIC: bi<=bj
//          tiles only; off-diagonal mirrored via smem-bounce transpose.
//   gemm2: out = sigmoid(S X) -> fp32

#define NROWS 8192
#define DDIM  1024

// ---- scratch (allocation-free rule => __device__ globals) ------------------
__device__ __nv_bfloat16 g_Xhi[(size_t)NROWS * DDIM];    // scaled rows
__device__ __nv_bfloat16 g_Xlo[(size_t)NROWS * DDIM];
__device__ __nv_bfloat16 g_XThi[(size_t)DDIM * NROWS];   // unscaled transpose
__device__ __nv_bfloat16 g_XTlo[(size_t)DDIM * NROWS];
__device__ __nv_bfloat16 g_Shi[(size_t)NROWS * NROWS];
__device__ __nv_bfloat16 g_Slo[(size_t)NROWS * NROWS];
__device__ float g_rinv[NROWS];

// ---- helpers ---------------------------------------------------------------
__device__ __forceinline__ uint32_t smem_u32(const void* p) {
    uint32_t a;
    asm("{ .reg .u64 t; cvta.to.shared.u64 t, %1; cvt.u32.u64 %0, t; }"
        : "=r"(a) : "l"(p));
    return a;
}

__device__ __forceinline__ void cp_async16(uint32_t dst, const void* src) {
    asm volatile("cp.async.cg.shared.global [%0], [%1], 16;" :: "r"(dst), "l"(src));
}
#define CP_COMMIT() asm volatile("cp.async.commit_group;" ::: "memory")
#define CP_WAIT0()  asm volatile("cp.async.wait_group 0;" ::: "memory")

__device__ __forceinline__ void ldsm4(uint32_t* r, uint32_t addr) {
    asm volatile("ldmatrix.sync.aligned.m8n8.x4.shared.b16 {%0,%1,%2,%3}, [%4];"
                 : "=r"(r[0]), "=r"(r[1]), "=r"(r[2]), "=r"(r[3]) : "r"(addr));
}

__device__ __forceinline__ void mma16816(float* c, const uint32_t* a,
                                         uint32_t b0, uint32_t b1) {
    asm volatile(
        "mma.sync.aligned.m16n8k16.row.col.f32.bf16.bf16.f32 "
        "{%0,%1,%2,%3}, {%4,%5,%6,%7}, {%8,%9}, {%0,%1,%2,%3};"
        : "+f"(c[0]), "+f"(c[1]), "+f"(c[2]), "+f"(c[3])
        : "r"(a[0]), "r"(a[1]), "r"(a[2]), "r"(a[3]), "r"(b0), "r"(b1));
}

// ---- tiling ----------------------------------------------------------------
#define BM 128
#define BN 128
#define BK 32
#define LDS_E 40                    // smem row stride in elements (80 B, 16B-mult)
#define ATILE_B (128 * LDS_E * 2)   // 10240 B per tile
#define STAGE_B (4 * ATILE_B)       // Ahi,Alo,Bhi,Blo
#define DSMEM_BYTES (2 * STAGE_B)   // 81920 B
#define O_AHI 0
#define O_ALO ATILE_B
#define O_BHI (2 * ATILE_B)
#define O_BLO (3 * ATILE_B)

// ---------------------------------------------------------------------------
// Kernel 0: reciprocal row norms.
// ---------------------------------------------------------------------------
__global__ void norms_kernel(const float* __restrict__ x) {
    int row  = blockIdx.x * 8 + threadIdx.y;
    int lane = threadIdx.x;
    const float4* xr = reinterpret_cast<const float4*>(x + (size_t)row * DDIM);
    float s = 0.0f;
    #pragma unroll
    for (int i = 0; i < 8; i++) {
        float4 v = xr[lane + i * 32];
        s += v.x * v.x + v.y * v.y + v.z * v.z + v.w * v.w;
    }
    #pragma unroll
    for (int o = 16; o > 0; o >>= 1) s += __shfl_xor_sync(0xffffffffu, s, o);
    if (lane == 0) g_rinv[row] = 1.0f / sqrtf(s);
}

// ---------------------------------------------------------------------------
// Kernel 0b: split. Row-major scaled (Xhat), transposed unscaled (X^T).
// ---------------------------------------------------------------------------
__global__ void split_kernel(const float* __restrict__ x) {
    __shared__ __nv_bfloat16 thi[32][33];
    __shared__ __nv_bfloat16 tlo[32][33];
    int d0 = blockIdx.x * 32;
    int n0 = blockIdx.y * 32;
    int tx = threadIdx.x, ty = threadIdx.y;

    #pragma unroll
    for (int r = 0; r < 4; r++) {
        int n = ty + r * 8;
        size_t gi = (size_t)(n0 + n) * DDIM + d0 + tx;
        float f = x[gi];
        __nv_bfloat16 uhi = __float2bfloat16(f);
        thi[n][tx] = uhi;
        tlo[n][tx] = __float2bfloat16(f - __bfloat162float(uhi));
        float fs = f * g_rinv[n0 + n];
        __nv_bfloat16 shi = __float2bfloat16(fs);
        g_Xhi[gi] = shi;
        g_Xlo[gi] = __float2bfloat16(fs - __bfloat162float(shi));
    }
    __syncthreads();
    #pragma unroll
    for (int r = 0; r < 4; r++) {
        int d = ty + r * 8;
        size_t go = (size_t)(d0 + d) * NROWS + n0 + tx;
        g_XThi[go] = thi[tx][d];
        g_XTlo[go] = tlo[tx][d];
    }
}

// ---------------------------------------------------------------------------
// Mainloop: double-buffered cp.async + 3-pass bf16 mma.sync.
// ONE __syncthreads per chunk:
//   wait(load ch) -> BAR -> issue load(ch+1) -> compute(ch)
// WAR: load(ch+1) targets the buffer last read by compute(ch-1); every warp
// passed this BAR only after finishing compute(ch-1). RAW: wait+BAR precede
// compute(ch). Load(ch+1) overlaps compute(ch).
// ---------------------------------------------------------------------------
struct GemmPtrs {
    const __nv_bfloat16 *Ahi, *Alo, *Bhi, *Blo;
};

__device__ __forceinline__ void load_stage(
    uint8_t* smem, int stage, const GemmPtrs& P, size_t ldK, int k0, int tid)
{
    uint32_t sb = smem_u32(smem + stage * STAGE_B);
    const __nv_bfloat16* srcs[4] = {P.Ahi, P.Alo, P.Bhi, P.Blo};
    const int rbase = tid >> 2;        // 0..63
    const int ch    = tid & 3;         // 16B chunk within 64-elem row span
    #pragma unroll
    for (int t = 0; t < 8; t++) {
        const int tile = t >> 1;       // compile-time constant per iteration
        const int row  = (t & 1) * 64 + rbase;
        uint32_t daddr = sb + tile * ATILE_B + row * (LDS_E * 2) + ch * 16;
        const __nv_bfloat16* g = srcs[tile] + (size_t)row * ldK + k0 + ch * 8;
        cp_async16(daddr, g);
    }
}

__device__ __forceinline__ void compute_stage(
    uint8_t* smem, int stage, float acc[2][8][4],
    int wm, int wn, int lane)
{
    uint32_t sb = smem_u32(smem + stage * STAGE_B);
    int arow = wm * 32 + (lane & 15);            // + mi*16
    int acol8 = (lane >> 4) << 3;                // 0 or 8
    int brow = wn * 64 + (lane & 7) + ((lane >> 3) & 1) * 8;   // + n2*16
    int bcol8 = (lane >> 4) << 3;

    #pragma unroll
    for (int ks = 0; ks < BK; ks += 16) {
        uint32_t ahi[2][4], alo[2][4];
        #pragma unroll
        for (int mi = 0; mi < 2; mi++) {
            uint32_t off = (arow + mi * 16) * (LDS_E * 2) + (ks + acol8) * 2;
            ldsm4(ahi[mi], sb + O_AHI + off);
            ldsm4(alo[mi], sb + O_ALO + off);
        }
        uint32_t bhi[4][4], blo[4][4];
        #pragma unroll
        for (int n2 = 0; n2 < 4; n2++) {
            uint32_t off = (brow + n2 * 16) * (LDS_E * 2) + (ks + bcol8) * 2;
            ldsm4(bhi[n2], sb + O_BHI + off);
            ldsm4(blo[n2], sb + O_BLO + off);
        }
        #pragma unroll
        for (int mi = 0; mi < 2; mi++) {
            #pragma unroll
            for (int ni = 0; ni < 8; ni++) {
                int n2 = ni >> 1, o = ni & 1;
                uint32_t bh0 = bhi[n2][o], bh1 = bhi[n2][o + 2];
                uint32_t bl0 = blo[n2][o], bl1 = blo[n2][o + 2];
                mma16816(acc[mi][ni], ahi[mi], bh0, bh1);   // hi*hi
                mma16816(acc[mi][ni], ahi[mi], bl0, bl1);   // hi*lo
                mma16816(acc[mi][ni], alo[mi], bh0, bh1);   // lo*hi
            }
        }
    }
}

__device__ __forceinline__ void gemm_mainloop(
    uint8_t* smem, float acc[2][8][4], const GemmPtrs& P, size_t ldK,
    int NCH, int tid, int wm, int wn, int lane)
{
    load_stage(smem, 0, P, ldK, 0, tid);
    CP_COMMIT();
    for (int ch = 0; ch < NCH; ch++) {
        CP_WAIT0();
        __syncthreads();
        if (ch + 1 < NCH) {
            load_stage(smem, (ch + 1) & 1, P, ldK, (ch + 1) * BK, tid);
            CP_COMMIT();
        }
        compute_stage(smem, ch & 1, acc, wm, wn, lane);
    }
}

// ---------------------------------------------------------------------------
// Kernel 1: S = Xhat Xhat^T, stored bf16 hi/lo. Upper-triangular only;
// off-diagonal tiles mirrored to (bj,bi) via smem-bounce transpose.
// ---------------------------------------------------------------------------
__global__ __launch_bounds__(256, 2) void gemm1_kernel() {
    extern __shared__ uint8_t smem[];
    const int bi = blockIdx.y, bj = blockIdx.x;
    if (bi > bj) return;   // uniform per-CTA: lower triangle handled by mirror

    const int tid  = threadIdx.x;
    const int lane = tid & 31;
    const int w    = tid >> 5;
    const int wm   = w & 3, wn = w >> 2;

    float acc[2][8][4];
    #pragma unroll
    for (int i = 0; i < 2; i++)
        #pragma unroll
        for (int j = 0; j < 8; j++)
            #pragma unroll
            for (int k = 0; k < 4; k++) acc[i][j][k] = 0.0f;

    GemmPtrs P;
    P.Ahi = g_Xhi + (size_t)(bi * BM) * DDIM;
    P.Alo = g_Xlo + (size_t)(bi * BM) * DDIM;
    P.Bhi = g_Xhi + (size_t)(bj * BN) * DDIM;
    P.Blo = g_Xlo + (size_t)(bj * BN) * DDIM;

    gemm_mainloop(smem, acc, P, DDIM, DDIM / BK, tid, wm, wn, lane);

    // Normal epilogue: write tile (bi, bj). acc IS the cosine similarity.
    int r0 = wm * 32 + (lane >> 2);
    int c0 = wn * 64 + (lane & 3) * 2;
    #pragma unroll
    for (int mi = 0; mi < 2; mi++) {
        #pragma unroll
        for (int half = 0; half < 2; half++) {
            int ig = bi * BM + r0 + mi * 16 + half * 8;
            size_t rowoff = (size_t)ig * NROWS;
            #pragma unroll
            for (int nj = 0; nj < 8; nj++) {
                int j = bj * BN + c0 + nj * 8;
                float f0 = acc[mi][nj][half * 2 + 0];
                float f1 = acc[mi][nj][half * 2 + 1];
                __nv_bfloat16 h0 = __float2bfloat16(f0);
                __nv_bfloat16 h1 = __float2bfloat16(f1);
                __nv_bfloat162 ph, pl;
                ph.x = h0; ph.y = h1;
                pl.x = __float2bfloat16(f0 - __bfloat162float(h0));
                pl.y = __float2bfloat16(f1 - __bfloat162float(h1));
                *reinterpret_cast<__nv_bfloat162*>(g_Shi + rowoff + j) = ph;
                *reinterpret_cast<__nv_bfloat162*>(g_Slo + rowoff + j) = pl;
            }
        }
    }

    // Mirror epilogue: tile (bj, bi) = transpose, via smem bounce.
    if (bi != bj) {
        const int LDT = 136;   // 272 B rows (16B multiple -> aligned uint4 reads)
        __nv_bfloat16* smT = reinterpret_cast<__nv_bfloat16*>(smem); // [128][LDT]
        const int oc = tid >> 1;      // mirrored row index (= original col)
        const int oh = tid & 1;       // half of 128 cols
        __nv_bfloat16* dsts[2] = {g_Shi, g_Slo};

        #pragma unroll
        for (int phase = 0; phase < 2; phase++) {
            __syncthreads();   // smem free (mainloop done / prev gather done)
            #pragma unroll
            for (int mi = 0; mi < 2; mi++) {
                #pragma unroll
                for (int half = 0; half < 2; half++) {
                    int r = r0 + mi * 16 + half * 8;
                    #pragma unroll
                    for (int nj = 0; nj < 8; nj++) {
                        int c = c0 + nj * 8;
                        float f0 = acc[mi][nj][half * 2 + 0];
                        float f1 = acc[mi][nj][half * 2 + 1];
                        __nv_bfloat16 v0, v1;
                        if (phase == 0) {
                            v0 = __float2bfloat16(f0);
                            v1 = __float2bfloat16(f1);
                        } else {
                            __nv_bfloat16 h0 = __float2bfloat16(f0);
                            __nv_bfloat16 h1 = __float2bfloat16(f1);
                            v0 = __float2bfloat16(f0 - __bfloat162float(h0));
                            v1 = __float2bfloat16(f1 - __bfloat162float(h1));
                        }
                        smT[(c + 0) * LDT + r] = v0;
                        smT[(c + 1) * LDT + r] = v1;
                    }
                }
            }
            __syncthreads();
            __nv_bfloat16* dst = dsts[phase]
                + (size_t)(bj * BN + oc) * NROWS + bi * BM + oh * 64;
            const uint8_t* srow = reinterpret_cast<const uint8_t*>(
                smT + oc * LDT + oh * 64);
            #pragma unroll
            for (int k = 0; k < 8; k++) {
                *reinterpret_cast<uint4*>(dst + k * 8) =
                    *reinterpret_cast<const uint4*>(srow + k * 16);
            }
        }
    }
}

// ---------------------------------------------------------------------------
// Kernel 2: out = sigmoid(S @ X). A=S (hi/lo), B=XT unscaled (hi/lo), K=8192.
// ---------------------------------------------------------------------------
__global__ __launch_bounds__(256, 2) void gemm2_kernel(float* __restrict__ out) {
    extern __shared__ uint8_t smem[];
    const int tid  = threadIdx.x;
    const int lane = tid & 31;
    const int w    = tid >> 5;
    const int wm   = w & 3, wn = w >> 2;
    const int bm = blockIdx.y, bn = blockIdx.x;

    float acc[2][8][4];
    #pragma unroll
    for (int i = 0; i < 2; i++)
        #pragma unroll
        for (int j = 0; j < 8; j++)
            #pragma unroll
            for (int k = 0; k < 4; k++) acc[i][j][k] = 0.0f;

    GemmPtrs P;
    P.Ahi = g_Shi + (size_t)(bm * BM) * NROWS;
    P.Alo = g_Slo + (size_t)(bm * BM) * NROWS;
    P.Bhi = g_XThi + (size_t)(bn * BN) * NROWS;
    P.Blo = g_XTlo + (size_t)(bn * BN) * NROWS;

    gemm_mainloop(smem, acc, P, NROWS, NROWS / BK, tid, wm, wn, lane);

    int r0 = wm * 32 + (lane >> 2);
    int c0 = wn * 64 + (lane & 3) * 2;
    #pragma unroll
    for (int mi = 0; mi < 2; mi++) {
        #pragma unroll
        for (int half = 0; half < 2; half++) {
            int ig = bm * BM + r0 + mi * 16 + half * 8;
            size_t rowoff = (size_t)ig * DDIM;
            #pragma unroll
            for (int nj = 0; nj < 8; nj++) {
                int j = bn * BN + c0 + nj * 8;
                float2 v;
                v.x = 1.0f / (1.0f + __expf(-acc[mi][nj][half * 2 + 0]));
                v.y = 1.0f / (1.0f + __expf(-acc[mi][nj][half * 2 + 1]));
                *reinterpret_cast<float2*>(out + rowoff + j) = v;
            }
        }
    }
}

// ---------------------------------------------------------------------------
extern "C" void kernel_launch(void* const* d_in, const int* in_sizes, int n_in,
                              void* d_out, int out_size) {
    const float* x = (const float*)d_in[0];
    float* out = (float*)d_out;

    cudaFuncSetAttribute(gemm1_kernel,
                         cudaFuncAttributeMaxDynamicSharedMemorySize, DSMEM_BYTES);
    cudaFuncSetAttribute(gemm2_kernel,
                         cudaFuncAttributeMaxDynamicSharedMemorySize, DSMEM_BYTES);

    norms_kernel<<<NROWS / 8, dim3(32, 8)>>>(x);
    split_kernel<<<dim3(DDIM / 32, NROWS / 32), dim3(32, 8)>>>(x);
    gemm1_kernel<<<dim3(NROWS / BN, NROWS / BM), 256, DSMEM_BYTES>>>();
    gemm2_kernel<<<dim3(DDIM / BN, NROWS / BM), 256, DSMEM_BYTES>>>(out);
}